// round 3
// baseline (speedup 1.0000x reference)
#include <cuda_runtime.h>
#include <math.h>

// Problem constants (MultiKAN: WIDTH=[512,512,512,512], GRID_SIZE=5, K=3, BATCH=1024)
#define BATCH 1024
#define IN    512
#define OUT   512
#define NC    8          // GRID_SIZE + K spline coefficients
#define NB    9          // 1 base (silu) + NC spline features per input unit
#define KK    (IN * NB)  // 4608 = GEMM K dimension
#define NG    12         // extended grid points per input unit

// Scratch (device globals; no allocation allowed)
__device__ float g_phi[BATCH * KK];   // 18.9 MB activations
__device__ float g_W[KK * OUT];       //  9.4 MB folded weights
__device__ float g_x[BATCH * IN];     //  2.1 MB inter-layer buffer

// ---------------------------------------------------------------------------
// Fold weights: W[(i*9+0), o] = sb[i,o]; W[(i*9+1+k), o] = sp[i,o]*coef[i,o,k]
// ---------------------------------------------------------------------------
__global__ void fold_kernel(const float* __restrict__ coef,
                            const float* __restrict__ sb,
                            const float* __restrict__ sp,
                            float* __restrict__ W) {
    int idx = blockIdx.x * blockDim.x + threadIdx.x;  // i*OUT + o
    if (idx >= IN * OUT) return;
    int i = idx / OUT, o = idx % OUT;
    float s_b = sb[idx];
    float s_p = sp[idx];
    W[(i * NB + 0) * OUT + o] = s_b;
    const float* c = coef + (size_t)idx * NC;
#pragma unroll
    for (int k = 0; k < NC; k++)
        W[(i * NB + 1 + k) * OUT + o] = s_p * c[k];
}

// ---------------------------------------------------------------------------
// Features: phi[(b*IN+i)*9 + {0..8}] = [silu(x), B-spline basis (degree 3)]
// Exactly replicates the reference Cox-de Boor recursion on the given grid.
// ---------------------------------------------------------------------------
__global__ void phi_kernel(const float* __restrict__ x,
                           const float* __restrict__ grid,
                           float* __restrict__ phi) {
    int idx = blockIdx.x * blockDim.x + threadIdx.x;  // b*IN + i
    if (idx >= BATCH * IN) return;
    int i = idx % IN;
    float xv = x[idx];

    float g[NG];
#pragma unroll
    for (int j = 0; j < NG; j++) g[j] = grid[i * NG + j];

    float Bv[NG - 1];
#pragma unroll
    for (int j = 0; j < NG - 1; j++)
        Bv[j] = (xv >= g[j] && xv < g[j + 1]) ? 1.0f : 0.0f;

#pragma unroll
    for (int p = 1; p <= 3; p++) {
#pragma unroll
        for (int j = 0; j + p < NG - 1; j++) {
            Bv[j] = (xv - g[j]) / (g[j + p] - g[j]) * Bv[j]
                  + (g[j + p + 1] - xv) / (g[j + p + 1] - g[j + 1]) * Bv[j + 1];
        }
    }

    float base = xv / (1.0f + expf(-xv));  // silu

    float* out = phi + (size_t)idx * NB;
    out[0] = base;
#pragma unroll
    for (int k = 0; k < NC; k++) out[1 + k] = Bv[k];
}

// ---------------------------------------------------------------------------
// SGEMM: C[M,N] = A[M,K] * B[K,N], fp32 accum, packed fma.rn.f32x2 inner loop
// BM=BN=64, BK=32, 256 threads (16x16), 4x4 per thread (as 4x2 f32x2 pairs).
// Grid: (N/64=8, M/64=16) = 128 CTAs, one wave on 148 SMs.
// ---------------------------------------------------------------------------
#define BM 64
#define BN 64
#define BK 32

__device__ __forceinline__ unsigned long long ffma2(unsigned long long a,
                                                    unsigned long long b,
                                                    unsigned long long c) {
    unsigned long long d;
    asm("fma.rn.f32x2 %0, %1, %2, %3;" : "=l"(d) : "l"(a), "l"(b), "l"(c));
    return d;
}

__device__ __forceinline__ unsigned long long pack2(float x) {
    unsigned long long d;
    asm("mov.b64 %0, {%1, %1};" : "=l"(d) : "f"(x));
    return d;
}

__global__ __launch_bounds__(256, 2)
void gemm_kernel(const float* __restrict__ A,   // [M, Kdim] row-major
                 const float* __restrict__ Bm,  // [Kdim, N] row-major
                 float* __restrict__ C,         // [M, N]
                 int M, int N, int Kdim) {
    __shared__ float As[BK][BM + 4];  // +4 keeps 16B alignment for v4 LDS
    __shared__ float Bs[BK][BN];

    int tid = threadIdx.x;
    int tx = tid & 15;        // 0..15 -> n
    int ty = tid >> 4;        // 0..15 -> m
    int block_m = blockIdx.y * BM;
    int block_n = blockIdx.x * BN;

    unsigned long long acc[4][2];
#pragma unroll
    for (int m = 0; m < 4; m++) {
        acc[m][0] = 0ULL;
        acc[m][1] = 0ULL;
    }

    // A-tile load mapping: 64x32 floats = 512 float4; 2 per thread
    int a_slot0 = tid;              // slots tid, tid+256
    // B-tile load mapping: 32x64 floats = 512 float4; 2 per thread

    int ntiles = Kdim / BK;
    for (int kt = 0; kt < ntiles; kt++) {
        int k0 = kt * BK;
        // Load A tile (transpose into As[k][m])
#pragma unroll
        for (int t = 0; t < 2; t++) {
            int slot = a_slot0 + t * 256;
            int row = slot >> 3;            // 0..63 (m)
            int kc  = (slot & 7) << 2;      // 0,4,...,28
            float4 v = *(const float4*)&A[(size_t)(block_m + row) * Kdim + k0 + kc];
            As[kc + 0][row] = v.x;
            As[kc + 1][row] = v.y;
            As[kc + 2][row] = v.z;
            As[kc + 3][row] = v.w;
        }
        // Load B tile (direct)
#pragma unroll
        for (int t = 0; t < 2; t++) {
            int slot = tid + t * 256;
            int row = slot >> 4;            // 0..31 (k)
            int col = (slot & 15) << 2;     // 0,4,...,60
            *(float4*)&Bs[row][col] =
                *(const float4*)&Bm[(size_t)(k0 + row) * N + block_n + col];
        }
        __syncthreads();

#pragma unroll
        for (int k = 0; k < BK; k++) {
            float4 a4 = *(const float4*)&As[k][ty * 4];
            ulonglong2 b2 = *(const ulonglong2*)&Bs[k][tx * 4];
            unsigned long long pa0 = pack2(a4.x);
            unsigned long long pa1 = pack2(a4.y);
            unsigned long long pa2 = pack2(a4.z);
            unsigned long long pa3 = pack2(a4.w);
            acc[0][0] = ffma2(pa0, b2.x, acc[0][0]);
            acc[0][1] = ffma2(pa0, b2.y, acc[0][1]);
            acc[1][0] = ffma2(pa1, b2.x, acc[1][0]);
            acc[1][1] = ffma2(pa1, b2.y, acc[1][1]);
            acc[2][0] = ffma2(pa2, b2.x, acc[2][0]);
            acc[2][1] = ffma2(pa2, b2.y, acc[2][1]);
            acc[3][0] = ffma2(pa3, b2.x, acc[3][0]);
            acc[3][1] = ffma2(pa3, b2.y, acc[3][1]);
        }
        __syncthreads();
    }

    // Write C: 4 rows x 4 cols per thread
#pragma unroll
    for (int m = 0; m < 4; m++) {
        float4 v;
        float2 lo = *(float2*)&acc[m][0];
        float2 hi = *(float2*)&acc[m][1];
        v.x = lo.x; v.y = lo.y; v.z = hi.x; v.w = hi.y;
        *(float4*)&C[(size_t)(block_m + ty * 4 + m) * N + block_n + tx * 4] = v;
    }
}

// ---------------------------------------------------------------------------
// Launch: 3 layers, each = fold + phi + gemm (sequential on one stream)
// ---------------------------------------------------------------------------
extern "C" void kernel_launch(void* const* d_in, const int* in_sizes, int n_in,
                              void* d_out, int out_size) {
    (void)in_sizes; (void)n_in; (void)out_size;

    float* phi_ptr = nullptr;
    float* w_ptr   = nullptr;
    float* x_ptr   = nullptr;
    cudaGetSymbolAddress((void**)&phi_ptr, g_phi);
    cudaGetSymbolAddress((void**)&w_ptr,   g_W);
    cudaGetSymbolAddress((void**)&x_ptr,   g_x);

    const float* xin = (const float*)d_in[0];

    for (int l = 0; l < 3; l++) {
        const float* grid = (const float*)d_in[1 + 4 * l];
        const float* coef = (const float*)d_in[2 + 4 * l];
        const float* sb   = (const float*)d_in[3 + 4 * l];
        const float* sp   = (const float*)d_in[4 + 4 * l];
        float* cout = (l == 2) ? (float*)d_out : x_ptr;

        fold_kernel<<<(IN * OUT + 255) / 256, 256>>>(coef, sb, sp, w_ptr);
        phi_kernel<<<(BATCH * IN + 255) / 256, 256>>>(xin, grid, phi_ptr);
        gemm_kernel<<<dim3(OUT / BN, BATCH / BM), 256>>>(phi_ptr, w_ptr, cout,
                                                         BATCH, OUT, KK);
        xin = x_ptr;
    }
}

// round 5
// speedup vs baseline: 1.4694x; 1.4694x over previous
#include <cuda_runtime.h>
#include <cuda_bf16.h>
#include <math.h>
#include <stdint.h>

// ===========================================================================
// MultiKAN: 3 layers of  out = phi(x) @ W.  M=1024, N=512, K=4608/layer.
// bf16 hi/lo 3-term split on warp-level mma.sync (base-PTX path; no tcgen05
// because the harness builds PTX at target sm_103, not sm_103a).
// ===========================================================================
#define BATCH 1024
#define IN    512
#define OUT   512
#define NC    8
#define NB    9
#define KDIM  (IN * NB)     // 4608
#define NG    12
#define KHALF (2 * KDIM)    // 9216  : stored K ( [hi | lo] )
#define KTOT  (3 * KDIM)    // 13824 : virtual K ( Ah*Bh + Al*Bh + Ah*Bl )
#define KSPLIT 4
#define KPER  (KTOT / KSPLIT)  // 3456
#define BK    32
#define NITER (KPER / BK)      // 108
#define STAGES 4
#define BM 128
#define BN 128
#define PADROW 40              // bf16 elems per smem row (32 data + 8 pad) = 80B
#define ATILE_B (128 * PADROW * 2)          // 10240 bytes
#define STAGE_B (2 * ATILE_B)               // A + B per stage
#define SMEM_SZ (STAGES * STAGE_B)          // 81920

__device__ __align__(16) __nv_bfloat16 g_A[(size_t)BATCH * KHALF];  // 18.9MB
__device__ __align__(16) __nv_bfloat16 g_Bt[(size_t)OUT * KHALF];   //  9.4MB
__device__ __align__(16) float g_part[(size_t)KSPLIT * BATCH * OUT]; // 8MB
__device__ float g_x[BATCH * IN];

__device__ __forceinline__ uint32_t smem_u32(const void* p) {
    uint32_t a;
    asm("{ .reg .u64 t; cvta.to.shared.u64 t, %1; cvt.u32.u64 %0, t; }"
        : "=r"(a) : "l"(p));
    return a;
}
__device__ __forceinline__ void cp16(uint32_t s, const void* g) {
    asm volatile("cp.async.ca.shared.global [%0], [%1], 16;"
                 :: "r"(s), "l"(g));
}
#define CP_COMMIT() asm volatile("cp.async.commit_group;")
#define CP_WAIT2()  asm volatile("cp.async.wait_group 2;")

__device__ __forceinline__ void ldmx4(uint32_t addr, uint32_t& r0, uint32_t& r1,
                                      uint32_t& r2, uint32_t& r3) {
    asm volatile("ldmatrix.sync.aligned.m8n8.x4.shared.b16 {%0,%1,%2,%3}, [%4];"
                 : "=r"(r0), "=r"(r1), "=r"(r2), "=r"(r3) : "r"(addr));
}
__device__ __forceinline__ void mma16816(float* d, const uint32_t* a,
                                         const uint32_t* b) {
    asm volatile(
        "mma.sync.aligned.m16n8k16.row.col.f32.bf16.bf16.f32 "
        "{%0,%1,%2,%3}, {%4,%5,%6,%7}, {%8,%9}, {%0,%1,%2,%3};"
        : "+f"(d[0]), "+f"(d[1]), "+f"(d[2]), "+f"(d[3])
        : "r"(a[0]), "r"(a[1]), "r"(a[2]), "r"(a[3]), "r"(b[0]), "r"(b[1]));
}

// ---------------------------------------------------------------------------
// fold: Bt[o][i*9+j] = hi/lo of W[k][o];  W row k=i*9: sb, then sp*coef
// ---------------------------------------------------------------------------
__global__ void fold_kernel(const float* __restrict__ coef,
                            const float* __restrict__ sb,
                            const float* __restrict__ sp) {
    int idx = blockIdx.x * blockDim.x + threadIdx.x;  // o*IN + i
    if (idx >= IN * OUT) return;
    int o = idx / IN, i = idx % IN;
    int io = i * OUT + o;
    float s_b = sb[io];
    float s_p = sp[io];
    const float* c = coef + (size_t)io * NC;

    float vals[NB];
    vals[0] = s_b;
#pragma unroll
    for (int k = 0; k < NC; k++) vals[1 + k] = s_p * c[k];

    __nv_bfloat16* row = g_Bt + (size_t)o * KHALF;
#pragma unroll
    for (int j = 0; j < NB; j++) {
        float v = vals[j];
        __nv_bfloat16 h = __float2bfloat16(v);
        __nv_bfloat16 l = __float2bfloat16(v - __bfloat162float(h));
        row[i * NB + j] = h;
        row[KDIM + i * NB + j] = l;
    }
}

// ---------------------------------------------------------------------------
// phi: A[b][i*9+j] = hi/lo of [silu(x), B-spline basis deg 3]
// ---------------------------------------------------------------------------
__global__ void phi_kernel(const float* __restrict__ x,
                           const float* __restrict__ grid) {
    int idx = blockIdx.x * blockDim.x + threadIdx.x;  // b*IN + i
    if (idx >= BATCH * IN) return;
    int b = idx / IN, i = idx % IN;
    float xv = x[idx];

    float g[NG];
#pragma unroll
    for (int j = 0; j < NG; j++) g[j] = grid[i * NG + j];

    float Bv[NG - 1];
#pragma unroll
    for (int j = 0; j < NG - 1; j++)
        Bv[j] = (xv >= g[j] && xv < g[j + 1]) ? 1.0f : 0.0f;
#pragma unroll
    for (int p = 1; p <= 3; p++) {
#pragma unroll
        for (int j = 0; j + p < NG - 1; j++) {
            Bv[j] = (xv - g[j]) / (g[j + p] - g[j]) * Bv[j]
                  + (g[j + p + 1] - xv) / (g[j + p + 1] - g[j + 1]) * Bv[j + 1];
        }
    }

    float vals[NB];
    vals[0] = xv / (1.0f + expf(-xv));
#pragma unroll
    for (int k = 0; k < NC; k++) vals[1 + k] = Bv[k];

    __nv_bfloat16* row = g_A + (size_t)b * KHALF;
#pragma unroll
    for (int j = 0; j < NB; j++) {
        float v = vals[j];
        __nv_bfloat16 h = __float2bfloat16(v);
        __nv_bfloat16 l = __float2bfloat16(v - __bfloat162float(h));
        row[i * NB + j] = h;
        row[KDIM + i * NB + j] = l;
    }
}

// ---------------------------------------------------------------------------
// GEMM: Cpart[ks][1024][512] += A'[1024][13824] * B'^T over k-split chunk.
// 128x128 tile, BK=32, 8 warps (4m x 2n, warp tile 32x64), m16n8k16 bf16.
// ---------------------------------------------------------------------------
__global__ void __launch_bounds__(256, 1)
gemm_kernel(const __nv_bfloat16* __restrict__ Ag,
            const __nv_bfloat16* __restrict__ Bg,
            float* __restrict__ Cpart) {
    extern __shared__ char smem[];
    uint32_t sbase = smem_u32(smem);

    int tid = threadIdx.x;
    int wid = tid >> 5;
    int lane = tid & 31;
    int wm = wid & 3;          // m quadrant (32 rows)
    int wn = wid >> 2;         // n half (64 cols)
    int n_tile = blockIdx.x;   // 0..3
    int m_tile = blockIdx.y;   // 0..7
    int ks = blockIdx.z;       // 0..3
    int m0 = m_tile * BM;
    int n0 = n_tile * BN;

    // --- async-load mapping: threads 0-127 -> A rows, 128-255 -> B rows ---
    int lrow = tid & 127;
    bool isB = tid >= 128;
    const __nv_bfloat16* grow =
        isB ? Bg + (size_t)(n0 + lrow) * KHALF
            : Ag + (size_t)(m0 + lrow) * KHALF;
    uint32_t srow = sbase + (isB ? ATILE_B : 0) + lrow * (PADROW * 2);

    float acc[2][8][4];
#pragma unroll
    for (int mt = 0; mt < 2; mt++)
#pragma unroll
        for (int nt = 0; nt < 8; nt++)
#pragma unroll
            for (int r = 0; r < 4; r++) acc[mt][nt][r] = 0.f;

    // ldmatrix source addresses (per-stage offset added later)
    // A: row = wm*32 + mt*16 + (lane%16), col bytes = kstep*32 + (lane/16)*16
    uint32_t aAddr = sbase + (wm * 32 + (lane & 15)) * (PADROW * 2)
                   + (lane >> 4) * 16;
    // B: row n = wn*64 + nt2*16 + (lane%8) + 8*(lane/16),
    //    col bytes = kstep*32 + ((lane/8)%2)*16
    uint32_t bAddr = sbase + ATILE_B
                   + (wn * 64 + (lane & 7) + ((lane >> 4) << 3)) * (PADROW * 2)
                   + (((lane >> 3) & 1) << 4);

#define ISSUE(t)                                                           \
    {                                                                      \
        int k0 = ks * KPER + (t) * BK;                                     \
        int kx = isB ? (k0 >= KDIM ? k0 - KDIM : k0)                       \
                     : (k0 >= KHALF ? k0 - KHALF : k0);                    \
        const __nv_bfloat16* gp = grow + kx;                               \
        uint32_t sp_ = srow + ((t) % STAGES) * STAGE_B;                    \
        cp16(sp_,      gp);                                                \
        cp16(sp_ + 16, gp + 8);                                            \
        cp16(sp_ + 32, gp + 16);                                           \
        cp16(sp_ + 48, gp + 24);                                           \
    }

#pragma unroll
    for (int t = 0; t < STAGES - 1; t++) { ISSUE(t); CP_COMMIT(); }

    for (int t = 0; t < NITER; t++) {
        CP_WAIT2();
        __syncthreads();
        if (t + STAGES - 1 < NITER) { ISSUE(t + STAGES - 1); }
        CP_COMMIT();

        uint32_t soff = (t % STAGES) * STAGE_B;
#pragma unroll
        for (int kk = 0; kk < 2; kk++) {       // two k16 steps per BK
            uint32_t a[2][4];
            ldmx4(aAddr + soff + kk * 32,                  a[0][0], a[0][1], a[0][2], a[0][3]);
            ldmx4(aAddr + soff + kk * 32 + 16 * PADROW * 2, a[1][0], a[1][1], a[1][2], a[1][3]);
            uint32_t b[4][4];                  // [nt16][t0b0,t0b1,t1b0,t1b1]
#pragma unroll
            for (int q = 0; q < 4; q++)
                ldmx4(bAddr + soff + kk * 32 + q * 16 * PADROW * 2,
                      b[q][0], b[q][1], b[q][2], b[q][3]);
#pragma unroll
            for (int mt = 0; mt < 2; mt++)
#pragma unroll
                for (int nt = 0; nt < 8; nt++)
                    mma16816(acc[mt][nt], a[mt], &b[nt >> 1][(nt & 1) * 2]);
        }
        __syncthreads();
    }

    // Epilogue: write partials (deterministic; reduced by reduce_kernel)
    float* C = Cpart + (size_t)ks * BATCH * OUT;
#pragma unroll
    for (int mt = 0; mt < 2; mt++) {
        int row = m0 + wm * 32 + mt * 16 + (lane >> 2);
#pragma unroll
        for (int nt = 0; nt < 8; nt++) {
            int col = n0 + wn * 64 + nt * 8 + (lane & 3) * 2;
            *(float2*)&C[(size_t)row * OUT + col] =
                make_float2(acc[mt][nt][0], acc[mt][nt][1]);
            *(float2*)&C[(size_t)(row + 8) * OUT + col] =
                make_float2(acc[mt][nt][2], acc[mt][nt][3]);
        }
    }
#undef ISSUE
}

// ---------------------------------------------------------------------------
// reduce: out = sum of 4 k-split partials (fixed order -> deterministic)
// ---------------------------------------------------------------------------
__global__ void reduce_kernel(const float* __restrict__ part,
                              float* __restrict__ out) {
    int idx = blockIdx.x * blockDim.x + threadIdx.x;
    if (idx >= BATCH * OUT / 4) return;
    const float4* p = (const float4*)part;
    float4 a = p[idx];
    float4 b = p[idx + BATCH * OUT / 4];
    float4 c = p[idx + 2 * (BATCH * OUT / 4)];
    float4 d = p[idx + 3 * (BATCH * OUT / 4)];
    float4 r;
    r.x = (a.x + b.x) + (c.x + d.x);
    r.y = (a.y + b.y) + (c.y + d.y);
    r.z = (a.z + b.z) + (c.z + d.z);
    r.w = (a.w + b.w) + (c.w + d.w);
    ((float4*)out)[idx] = r;
}

// ---------------------------------------------------------------------------
extern "C" void kernel_launch(void* const* d_in, const int* in_sizes, int n_in,
                              void* d_out, int out_size) {
    (void)in_sizes; (void)n_in; (void)out_size;

    __nv_bfloat16 *Aptr = nullptr, *Bptr = nullptr;
    float *pptr = nullptr, *xptr = nullptr;
    cudaGetSymbolAddress((void**)&Aptr, g_A);
    cudaGetSymbolAddress((void**)&Bptr, g_Bt);
    cudaGetSymbolAddress((void**)&pptr, g_part);
    cudaGetSymbolAddress((void**)&xptr, g_x);

    cudaFuncSetAttribute(gemm_kernel,
                         cudaFuncAttributeMaxDynamicSharedMemorySize, SMEM_SZ);

    const float* xin = (const float*)d_in[0];
    for (int l = 0; l < 3; l++) {
        const float* grid = (const float*)d_in[1 + 4 * l];
        const float* coef = (const float*)d_in[2 + 4 * l];
        const float* sbp  = (const float*)d_in[3 + 4 * l];
        const float* spp  = (const float*)d_in[4 + 4 * l];
        float* cout = (l == 2) ? (float*)d_out : xptr;

        fold_kernel<<<(IN * OUT + 255) / 256, 256>>>(coef, sbp, spp);
        phi_kernel<<<(BATCH * IN + 255) / 256, 256>>>(xin, grid);
        gemm_kernel<<<dim3(OUT / BN, BATCH / BM, KSPLIT), 256, SMEM_SZ>>>(
            Aptr, Bptr, pptr);
        reduce_kernel<<<(BATCH * OUT / 4 + 255) / 256, 256>>>(pptr, cout);
        xin = xptr;
    }
}

// round 7
// speedup vs baseline: 1.8730x; 1.2747x over previous
#include <cuda_runtime.h>
#include <cuda_fp16.h>
#include <math.h>
#include <stdint.h>

// ===========================================================================
// MultiKAN: 3 layers of out = phi(x) @ W.  M=1024, N=512, K=4608/layer.
// fp16 2-term hi/lo split + silu-column correction on warp-level mma.sync.
//   C = Ah*Bh + Al*Bh + (Ah_silu * Bl_silu)          virtual K' = 9728
// A storage per row: [Ah(4608) | Al(4608) | Ah_silu*2^-6 (512)]
// B storage per row: [Bh(4608) | Bl_silu*2^6 (512)]
//   kb = k0 < 4608 ? k0 : k0-4608   (uniform over all segments)
// ===========================================================================
#define BATCH 1024
#define IN    512
#define OUT   512
#define NC    8
#define NB    9
#define KDIM  (IN * NB)       // 4608
#define NG    12
#define KA    (2 * KDIM + IN) // 9728 : virtual K & A row length
#define KBROW (KDIM + IN)     // 5120 : B row length
#define KSPLIT 4
#define KPER  (KA / KSPLIT)   // 2432
#define BK    32
#define NITER (KPER / BK)     // 76
#define STAGES 4
#define BM 128
#define BN 128
#define PADROW 40             // halfs per smem row (32 data + 8 pad) = 80B
#define ATILE_B (128 * PADROW * 2)   // 10240 bytes
#define STAGE_B (2 * ATILE_B)
#define SMEM_SZ (STAGES * STAGE_B)   // 81920

__device__ __align__(16) __half g_A[(size_t)BATCH * KA];    // 19.9MB
__device__ __align__(16) __half g_Bt[(size_t)OUT * KBROW];  //  5.2MB
__device__ __align__(16) float g_part[(size_t)KSPLIT * BATCH * OUT]; // 8MB

__device__ __forceinline__ uint32_t smem_u32(const void* p) {
    uint32_t a;
    asm("{ .reg .u64 t; cvta.to.shared.u64 t, %1; cvt.u32.u64 %0, t; }"
        : "=r"(a) : "l"(p));
    return a;
}
__device__ __forceinline__ void cp16(uint32_t s, const void* g) {
    asm volatile("cp.async.ca.shared.global [%0], [%1], 16;"
                 :: "r"(s), "l"(g));
}
#define CP_COMMIT() asm volatile("cp.async.commit_group;")
#define CP_WAIT2()  asm volatile("cp.async.wait_group 2;")

__device__ __forceinline__ void ldmx4(uint32_t addr, uint32_t& r0, uint32_t& r1,
                                      uint32_t& r2, uint32_t& r3) {
    asm volatile("ldmatrix.sync.aligned.m8n8.x4.shared.b16 {%0,%1,%2,%3}, [%4];"
                 : "=r"(r0), "=r"(r1), "=r"(r2), "=r"(r3) : "r"(addr));
}
__device__ __forceinline__ void mma16816(float* d, const uint32_t* a,
                                         const uint32_t* b) {
    asm volatile(
        "mma.sync.aligned.m16n8k16.row.col.f32.f16.f16.f32 "
        "{%0,%1,%2,%3}, {%4,%5,%6,%7}, {%8,%9}, {%0,%1,%2,%3};"
        : "+f"(d[0]), "+f"(d[1]), "+f"(d[2]), "+f"(d[3])
        : "r"(a[0]), "r"(a[1]), "r"(a[2]), "r"(a[3]), "r"(b[0]), "r"(b[1]));
}

// ---------------------------------------------------------------------------
// fold: B row o: Bh at [i*9+j]; silu-weight residual (x64) at [4608 + i]
// ---------------------------------------------------------------------------
__global__ void fold_kernel(const float* __restrict__ coef,
                            const float* __restrict__ sb,
                            const float* __restrict__ sp) {
    int idx = blockIdx.x * blockDim.x + threadIdx.x;  // o*IN + i
    if (idx >= IN * OUT) return;
    int o = idx / IN, i = idx % IN;
    int io = i * OUT + o;
    float s_b = sb[io];
    float s_p = sp[io];
    const float* c = coef + (size_t)io * NC;

    __half* row = g_Bt + (size_t)o * KBROW;
    __half h0 = __float2half(s_b);
    row[i * NB] = h0;
    row[KDIM + i] = __float2half((s_b - __half2float(h0)) * 64.0f);
#pragma unroll
    for (int k = 0; k < NC; k++)
        row[i * NB + 1 + k] = __float2half(s_p * c[k]);
}

// ---------------------------------------------------------------------------
// phi core: vals = [silu(x), B-spline basis deg 3]; writes hi/lo + silu dup
// ---------------------------------------------------------------------------
__device__ __forceinline__ void phi_store(float xv, const float* __restrict__ grid,
                                          int b, int i) {
    float g[NG];
#pragma unroll
    for (int j = 0; j < NG; j++) g[j] = grid[i * NG + j];

    float Bv[NG - 1];
#pragma unroll
    for (int j = 0; j < NG - 1; j++)
        Bv[j] = (xv >= g[j] && xv < g[j + 1]) ? 1.0f : 0.0f;
#pragma unroll
    for (int p = 1; p <= 3; p++) {
#pragma unroll
        for (int j = 0; j + p < NG - 1; j++) {
            Bv[j] = (xv - g[j]) / (g[j + p] - g[j]) * Bv[j]
                  + (g[j + p + 1] - xv) / (g[j + p + 1] - g[j + 1]) * Bv[j + 1];
        }
    }

    float vals[NB];
    vals[0] = xv / (1.0f + expf(-xv));
#pragma unroll
    for (int k = 0; k < NC; k++) vals[1 + k] = Bv[k];

    __half* row = g_A + (size_t)b * KA;
#pragma unroll
    for (int j = 0; j < NB; j++) {
        float v = vals[j];
        __half h = __float2half(v);
        row[i * NB + j] = h;
        row[KDIM + i * NB + j] = __float2half(v - __half2float(h));
    }
    // silu hi duplicate, scaled 2^-6 (pairs with B residual scaled 2^6)
    row[2 * KDIM + i] = __float2half(__half2float(row[i * NB]) * 0.015625f);
}

__global__ void phi_first(const float* __restrict__ x,
                          const float* __restrict__ grid) {
    int idx = blockIdx.x * blockDim.x + threadIdx.x;  // b*IN + i
    if (idx >= BATCH * IN) return;
    phi_store(x[idx], grid, idx / IN, idx % IN);
}

// fused: reduce split-K partials of the previous layer inline
__global__ void phi_fused(const float* __restrict__ part,
                          const float* __restrict__ grid) {
    int idx = blockIdx.x * blockDim.x + threadIdx.x;  // b*IN + i
    if (idx >= BATCH * IN) return;
    float xv = (part[idx] + part[idx + BATCH * OUT])
             + (part[idx + 2 * BATCH * OUT] + part[idx + 3 * BATCH * OUT]);
    phi_store(xv, grid, idx / IN, idx % IN);
}

// ---------------------------------------------------------------------------
// GEMM: Cpart[ks][1024][512] = A'[1024][9728] * B'^T over k-split chunk.
// 128x128 tile, BK=32, 8 warps (4m x 2n, warp tile 32x64), m16n8k16 fp16.
// ---------------------------------------------------------------------------
__global__ void __launch_bounds__(256, 1)
gemm_kernel(const __half* __restrict__ Ag,
            const __half* __restrict__ Bg,
            float* __restrict__ Cpart) {
    extern __shared__ char smem[];
    uint32_t sbase = smem_u32(smem);

    int tid = threadIdx.x;
    int wid = tid >> 5;
    int lane = tid & 31;
    int wm = wid & 3;
    int wn = wid >> 2;
    int n_tile = blockIdx.x;   // 0..3
    int m_tile = blockIdx.y;   // 0..7
    int ks = blockIdx.z;       // 0..3
    int m0 = m_tile * BM;
    int n0 = n_tile * BN;

    int lrow = tid & 127;
    bool isB = tid >= 128;
    const __half* grow =
        isB ? Bg + (size_t)(n0 + lrow) * KBROW
            : Ag + (size_t)(m0 + lrow) * KA;
    uint32_t srow = sbase + (isB ? ATILE_B : 0) + lrow * (PADROW * 2);

    float acc[2][8][4];
#pragma unroll
    for (int mt = 0; mt < 2; mt++)
#pragma unroll
        for (int nt = 0; nt < 8; nt++)
#pragma unroll
            for (int r = 0; r < 4; r++) acc[mt][nt][r] = 0.f;

    uint32_t aAddr = sbase + (wm * 32 + (lane & 15)) * (PADROW * 2)
                   + (lane >> 4) * 16;
    uint32_t bAddr = sbase + ATILE_B
                   + (wn * 64 + (lane & 7) + ((lane >> 4) << 3)) * (PADROW * 2)
                   + (((lane >> 3) & 1) << 4);

#define ISSUE(t)                                                           \
    {                                                                      \
        int k0 = ks * KPER + (t) * BK;                                     \
        int kx = isB ? (k0 < KDIM ? k0 : k0 - KDIM) : k0;                  \
        const __half* gp = grow + kx;                                      \
        uint32_t sp_ = srow + ((t) % STAGES) * STAGE_B;                    \
        cp16(sp_,      gp);                                                \
        cp16(sp_ + 16, gp + 8);                                            \
        cp16(sp_ + 32, gp + 16);                                           \
        cp16(sp_ + 48, gp + 24);                                           \
    }

#pragma unroll
    for (int t = 0; t < STAGES - 1; t++) { ISSUE(t); CP_COMMIT(); }

    for (int t = 0; t < NITER; t++) {
        CP_WAIT2();
        __syncthreads();   // single sync: makes stage t visible AND fences
                           // all readers of stage (t-1)%4 before its rewrite
        if (t + STAGES - 1 < NITER) { ISSUE(t + STAGES - 1); }
        CP_COMMIT();

        uint32_t soff = (t % STAGES) * STAGE_B;
#pragma unroll
        for (int kk = 0; kk < 2; kk++) {
            uint32_t a[2][4];
            ldmx4(aAddr + soff + kk * 32,                   a[0][0], a[0][1], a[0][2], a[0][3]);
            ldmx4(aAddr + soff + kk * 32 + 16 * PADROW * 2, a[1][0], a[1][1], a[1][2], a[1][3]);
            uint32_t b[4][4];
#pragma unroll
            for (int q = 0; q < 4; q++)
                ldmx4(bAddr + soff + kk * 32 + q * 16 * PADROW * 2,
                      b[q][0], b[q][1], b[q][2], b[q][3]);
#pragma unroll
            for (int mt = 0; mt < 2; mt++)
#pragma unroll
                for (int nt = 0; nt < 8; nt++)
                    mma16816(acc[mt][nt], a[mt], &b[nt >> 1][(nt & 1) * 2]);
        }
    }

    float* C = Cpart + (size_t)ks * BATCH * OUT;
#pragma unroll
    for (int mt = 0; mt < 2; mt++) {
        int row = m0 + wm * 32 + mt * 16 + (lane >> 2);
#pragma unroll
        for (int nt = 0; nt < 8; nt++) {
            int col = n0 + wn * 64 + nt * 8 + (lane & 3) * 2;
            *(float2*)&C[(size_t)row * OUT + col] =
                make_float2(acc[mt][nt][0], acc[mt][nt][1]);
            *(float2*)&C[(size_t)(row + 8) * OUT + col] =
                make_float2(acc[mt][nt][2], acc[mt][nt][3]);
        }
    }
#undef ISSUE
}

// ---------------------------------------------------------------------------
// reduce: final layer only (deterministic fixed-order sum of 4 partials)
// ---------------------------------------------------------------------------
__global__ void reduce_kernel(const float* __restrict__ part,
                              float* __restrict__ out) {
    int idx = blockIdx.x * blockDim.x + threadIdx.x;
    if (idx >= BATCH * OUT / 4) return;
    const float4* p = (const float4*)part;
    float4 a = p[idx];
    float4 b = p[idx + BATCH * OUT / 4];
    float4 c = p[idx + 2 * (BATCH * OUT / 4)];
    float4 d = p[idx + 3 * (BATCH * OUT / 4)];
    float4 r;
    r.x = (a.x + b.x) + (c.x + d.x);
    r.y = (a.y + b.y) + (c.y + d.y);
    r.z = (a.z + b.z) + (c.z + d.z);
    r.w = (a.w + b.w) + (c.w + d.w);
    ((float4*)out)[idx] = r;
}

// ---------------------------------------------------------------------------
extern "C" void kernel_launch(void* const* d_in, const int* in_sizes, int n_in,
                              void* d_out, int out_size) {
    (void)in_sizes; (void)n_in; (void)out_size;

    __half *Aptr = nullptr, *Bptr = nullptr;
    float *pptr = nullptr;
    cudaGetSymbolAddress((void**)&Aptr, g_A);
    cudaGetSymbolAddress((void**)&Bptr, g_Bt);
    cudaGetSymbolAddress((void**)&pptr, g_part);

    cudaFuncSetAttribute(gemm_kernel,
                         cudaFuncAttributeMaxDynamicSharedMemorySize, SMEM_SZ);

    for (int l = 0; l < 3; l++) {
        const float* grid = (const float*)d_in[1 + 4 * l];
        const float* coef = (const float*)d_in[2 + 4 * l];
        const float* sbp  = (const float*)d_in[3 + 4 * l];
        const float* spp  = (const float*)d_in[4 + 4 * l];

        fold_kernel<<<(IN * OUT + 255) / 256, 256>>>(coef, sbp, spp);
        if (l == 0)
            phi_first<<<(BATCH * IN + 255) / 256, 256>>>((const float*)d_in[0], grid);
        else
            phi_fused<<<(BATCH * IN + 255) / 256, 256>>>(pptr, grid);
        gemm_kernel<<<dim3(OUT / BN, BATCH / BM, KSPLIT), 256, SMEM_SZ>>>(
            Aptr, Bptr, pptr);
    }
    reduce_kernel<<<(BATCH * OUT / 4 + 255) / 256, 256>>>(pptr, (float*)d_out);
}

// round 8
// speedup vs baseline: 2.1941x; 1.1714x over previous
#include <cuda_runtime.h>
#include <cuda_fp16.h>
#include <math.h>
#include <stdint.h>

// ===========================================================================
// MultiKAN: 3 layers of out = phi(x) @ W.  M=1024, N=512, K=4608/layer.
// fp16 split, silu-only correction terms (silu dominates output magnitude):
//   C = Ah*Bh (4608) + Al_silu*Bh_silu (512) + Ah_silu*Bl_silu (512)
// K' = 5632, fully linear layouts (no k remap):
//   A row: [Ah(4608) | Al_silu(512) | Ah_silu*2^-6(512)]
//   B row: [Bh(4608) | Bh_silu(512) | Bl_silu*2^6(512)]
// ===========================================================================
#define BATCH 1024
#define IN    512
#define OUT   512
#define NC    8
#define NB    9
#define KDIM  (IN * NB)        // 4608
#define NG    12
#define KROW  (KDIM + 2 * IN)  // 5632 : virtual K and row length (A and B)
#define KSPLIT 4
#define KPER  (KROW / KSPLIT)  // 1408
#define BK    32
#define NITER (KPER / BK)      // 44
#define STAGES 4
#define BM 128
#define BN 128
#define PADROW 40              // halfs per smem row (32 data + 8 pad) = 80B
#define ATILE_B (128 * PADROW * 2)   // 10240 bytes
#define STAGE_B (2 * ATILE_B)
#define SMEM_SZ (STAGES * STAGE_B)   // 81920

__device__ __align__(16) __half g_A[(size_t)BATCH * KROW];   // 11.5MB
__device__ __align__(16) __half g_Bt[(size_t)OUT * KROW];    //  5.8MB
__device__ __align__(16) float g_part[(size_t)KSPLIT * BATCH * OUT]; // 8MB

__device__ __forceinline__ uint32_t smem_u32(const void* p) {
    uint32_t a;
    asm("{ .reg .u64 t; cvta.to.shared.u64 t, %1; cvt.u32.u64 %0, t; }"
        : "=r"(a) : "l"(p));
    return a;
}
__device__ __forceinline__ void cp16(uint32_t s, const void* g) {
    asm volatile("cp.async.ca.shared.global [%0], [%1], 16;"
                 :: "r"(s), "l"(g));
}
#define CP_COMMIT() asm volatile("cp.async.commit_group;")
#define CP_WAIT2()  asm volatile("cp.async.wait_group 2;")

__device__ __forceinline__ void ldmx4(uint32_t addr, uint32_t& r0, uint32_t& r1,
                                      uint32_t& r2, uint32_t& r3) {
    asm volatile("ldmatrix.sync.aligned.m8n8.x4.shared.b16 {%0,%1,%2,%3}, [%4];"
                 : "=r"(r0), "=r"(r1), "=r"(r2), "=r"(r3) : "r"(addr));
}
__device__ __forceinline__ void mma16816(float* d, const uint32_t* a,
                                         const uint32_t* b) {
    asm volatile(
        "mma.sync.aligned.m16n8k16.row.col.f32.f16.f16.f32 "
        "{%0,%1,%2,%3}, {%4,%5,%6,%7}, {%8,%9}, {%0,%1,%2,%3};"
        : "+f"(d[0]), "+f"(d[1]), "+f"(d[2]), "+f"(d[3])
        : "r"(a[0]), "r"(a[1]), "r"(a[2]), "r"(a[3]), "r"(b[0]), "r"(b[1]));
}

// ---------------------------------------------------------------------------
// fold: smem-transpose tile (64 o x 32 i) -> coalesced reads AND writes.
// B row o: Bh[i*9+j]; Bh_silu dup at 4608+i; Bl_silu*64 at 5120+i.
// ---------------------------------------------------------------------------
#define FO 64
#define FI 32
#define FPITCH 296   // 288 data halfs + 8 pad (592B, 16B-aligned)

__global__ void __launch_bounds__(256, 4)
fold_kernel(const float* __restrict__ coef,
            const float* __restrict__ sb,
            const float* __restrict__ sp) {
    __shared__ __half s_hi[FO * FPITCH];   // 37888 B
    __shared__ __half s_sil[FO * FI];      // hi(sb)
    __shared__ __half s_res[FO * FI];      // (sb - hi)*64

    int tid = threadIdx.x;
    int o0 = blockIdx.x * FO;
    int i0 = blockIdx.y * FI;

    // Phase 1: coalesced reads (consecutive threads -> consecutive o)
#pragma unroll
    for (int r = 0; r < (FO * FI) / 256; r++) {      // 8 pairs/thread
        int lin = r * 256 + tid;
        int ol = lin & (FO - 1);
        int il = lin >> 6;
        int io = (i0 + il) * OUT + (o0 + ol);
        float s_b = sb[io];
        float s_p = sp[io];
        const float* c = coef + (size_t)io * NC;

        __half h0 = __float2half(s_b);
        s_sil[ol * FI + il] = h0;
        s_res[ol * FI + il] = __float2half((s_b - __half2float(h0)) * 64.0f);
        __half* dst = s_hi + ol * FPITCH + il * NB;
        dst[0] = h0;
#pragma unroll
        for (int k = 0; k < NC; k++)
            dst[1 + k] = __float2half(s_p * c[k]);
    }
    __syncthreads();

    // Phase 2: coalesced 16B writes of each output row span
    // hi spans: 64 rows x 36 float4
    for (int idx = tid; idx < FO * 36; idx += 256) {
        int ol = idx / 36, v = idx % 36;
        const float4* src = (const float4*)(s_hi + ol * FPITCH);
        float4* dst = (float4*)(g_Bt + (size_t)(o0 + ol) * KROW + i0 * NB);
        dst[v] = src[v];
    }
    // silu dup + residual spans: 64 rows x 4 float4 each
    for (int idx = tid; idx < FO * 4; idx += 256) {
        int ol = idx >> 2, v = idx & 3;
        __half* row = g_Bt + (size_t)(o0 + ol) * KROW;
        ((float4*)(row + KDIM + i0))[v]      = ((const float4*)(s_sil + ol * FI))[v];
        ((float4*)(row + KDIM + IN + i0))[v] = ((const float4*)(s_res + ol * FI))[v];
    }
}

// ---------------------------------------------------------------------------
// phi: A row b: Ah[i*9+j]; Al_silu at 4608+i; Ah_silu*2^-6 at 5120+i
// ---------------------------------------------------------------------------
__device__ __forceinline__ void phi_store(float xv, const float* __restrict__ grid,
                                          int b, int i) {
    float g[NG];
#pragma unroll
    for (int j = 0; j < NG; j++) g[j] = grid[i * NG + j];

    float Bv[NG - 1];
#pragma unroll
    for (int j = 0; j < NG - 1; j++)
        Bv[j] = (xv >= g[j] && xv < g[j + 1]) ? 1.0f : 0.0f;
#pragma unroll
    for (int p = 1; p <= 3; p++) {
#pragma unroll
        for (int j = 0; j + p < NG - 1; j++) {
            Bv[j] = (xv - g[j]) / (g[j + p] - g[j]) * Bv[j]
                  + (g[j + p + 1] - xv) / (g[j + p + 1] - g[j + 1]) * Bv[j + 1];
        }
    }

    float base = xv / (1.0f + expf(-xv));
    __half* row = g_A + (size_t)b * KROW;
    __half bh = __float2half(base);
    row[i * NB] = bh;
#pragma unroll
    for (int k = 0; k < NC; k++)
        row[i * NB + 1 + k] = __float2half(Bv[k]);
    row[KDIM + i] = __float2half(base - __half2float(bh));        // Al_silu
    row[KDIM + IN + i] = __float2half(__half2float(bh) * 0.015625f); // Ah*2^-6
}

__global__ void phi_first(const float* __restrict__ x,
                          const float* __restrict__ grid) {
    int idx = blockIdx.x * blockDim.x + threadIdx.x;
    if (idx >= BATCH * IN) return;
    phi_store(x[idx], grid, idx / IN, idx % IN);
}

__global__ void phi_fused(const float* __restrict__ part,
                          const float* __restrict__ grid) {
    int idx = blockIdx.x * blockDim.x + threadIdx.x;
    if (idx >= BATCH * IN) return;
    float xv = (part[idx] + part[idx + BATCH * OUT])
             + (part[idx + 2 * BATCH * OUT] + part[idx + 3 * BATCH * OUT]);
    phi_store(xv, grid, idx / IN, idx % IN);
}

// ---------------------------------------------------------------------------
// GEMM: Cpart[ks][1024][512] = A'[1024][5632] * B'^T over k-split chunk.
// 128x128 tile, BK=32, 8 warps (4m x 2n), m16n8k16 fp16, linear K (no remap).
// ---------------------------------------------------------------------------
__global__ void __launch_bounds__(256, 1)
gemm_kernel(const __half* __restrict__ Ag,
            const __half* __restrict__ Bg,
            float* __restrict__ Cpart) {
    extern __shared__ char smem[];
    uint32_t sbase = smem_u32(smem);

    int tid = threadIdx.x;
    int wid = tid >> 5;
    int lane = tid & 31;
    int wm = wid & 3;
    int wn = wid >> 2;
    int n_tile = blockIdx.x;
    int m_tile = blockIdx.y;
    int ks = blockIdx.z;
    int m0 = m_tile * BM;
    int n0 = n_tile * BN;

    int lrow = tid & 127;
    bool isB = tid >= 128;
    const __half* grow =
        (isB ? Bg + (size_t)(n0 + lrow) * KROW
             : Ag + (size_t)(m0 + lrow) * KROW) + ks * KPER;
    uint32_t srow = sbase + (isB ? ATILE_B : 0) + lrow * (PADROW * 2);

    float acc[2][8][4];
#pragma unroll
    for (int mt = 0; mt < 2; mt++)
#pragma unroll
        for (int nt = 0; nt < 8; nt++)
#pragma unroll
            for (int r = 0; r < 4; r++) acc[mt][nt][r] = 0.f;

    uint32_t aAddr = sbase + (wm * 32 + (lane & 15)) * (PADROW * 2)
                   + (lane >> 4) * 16;
    uint32_t bAddr = sbase + ATILE_B
                   + (wn * 64 + (lane & 7) + ((lane >> 4) << 3)) * (PADROW * 2)
                   + (((lane >> 3) & 1) << 4);

#define ISSUE(t)                                                           \
    {                                                                      \
        const __half* gp = grow + (t) * BK;                                \
        uint32_t sp_ = srow + ((t) % STAGES) * STAGE_B;                    \
        cp16(sp_,      gp);                                                \
        cp16(sp_ + 16, gp + 8);                                            \
        cp16(sp_ + 32, gp + 16);                                           \
        cp16(sp_ + 48, gp + 24);                                           \
    }

#pragma unroll
    for (int t = 0; t < STAGES - 1; t++) { ISSUE(t); CP_COMMIT(); }

    for (int t = 0; t < NITER; t++) {
        CP_WAIT2();
        __syncthreads();
        if (t + STAGES - 1 < NITER) { ISSUE(t + STAGES - 1); }
        CP_COMMIT();

        uint32_t soff = (t % STAGES) * STAGE_B;
#pragma unroll
        for (int kk = 0; kk < 2; kk++) {
            uint32_t a[2][4];
            ldmx4(aAddr + soff + kk * 32,                   a[0][0], a[0][1], a[0][2], a[0][3]);
            ldmx4(aAddr + soff + kk * 32 + 16 * PADROW * 2, a[1][0], a[1][1], a[1][2], a[1][3]);
            uint32_t b[4][4];
#pragma unroll
            for (int q = 0; q < 4; q++)
                ldmx4(bAddr + soff + kk * 32 + q * 16 * PADROW * 2,
                      b[q][0], b[q][1], b[q][2], b[q][3]);
#pragma unroll
            for (int mt = 0; mt < 2; mt++)
#pragma unroll
                for (int nt = 0; nt < 8; nt++)
                    mma16816(acc[mt][nt], a[mt], &b[nt >> 1][(nt & 1) * 2]);
        }
    }

    float* C = Cpart + (size_t)ks * BATCH * OUT;
#pragma unroll
    for (int mt = 0; mt < 2; mt++) {
        int row = m0 + wm * 32 + mt * 16 + (lane >> 2);
#pragma unroll
        for (int nt = 0; nt < 8; nt++) {
            int col = n0 + wn * 64 + nt * 8 + (lane & 3) * 2;
            *(float2*)&C[(size_t)row * OUT + col] =
                make_float2(acc[mt][nt][0], acc[mt][nt][1]);
            *(float2*)&C[(size_t)(row + 8) * OUT + col] =
                make_float2(acc[mt][nt][2], acc[mt][nt][3]);
        }
    }
#undef ISSUE
}

// ---------------------------------------------------------------------------
// reduce: final layer only (deterministic fixed-order sum of 4 partials)
// ---------------------------------------------------------------------------
__global__ void reduce_kernel(const float* __restrict__ part,
                              float* __restrict__ out) {
    int idx = blockIdx.x * blockDim.x + threadIdx.x;
    if (idx >= BATCH * OUT / 4) return;
    const float4* p = (const float4*)part;
    float4 a = p[idx];
    float4 b = p[idx + BATCH * OUT / 4];
    float4 c = p[idx + 2 * (BATCH * OUT / 4)];
    float4 d = p[idx + 3 * (BATCH * OUT / 4)];
    float4 r;
    r.x = (a.x + b.x) + (c.x + d.x);
    r.y = (a.y + b.y) + (c.y + d.y);
    r.z = (a.z + b.z) + (c.z + d.z);
    r.w = (a.w + b.w) + (c.w + d.w);
    ((float4*)out)[idx] = r;
}

// ---------------------------------------------------------------------------
extern "C" void kernel_launch(void* const* d_in, const int* in_sizes, int n_in,
                              void* d_out, int out_size) {
    (void)in_sizes; (void)n_in; (void)out_size;

    __half *Aptr = nullptr, *Bptr = nullptr;
    float *pptr = nullptr;
    cudaGetSymbolAddress((void**)&Aptr, g_A);
    cudaGetSymbolAddress((void**)&Bptr, g_Bt);
    cudaGetSymbolAddress((void**)&pptr, g_part);

    cudaFuncSetAttribute(gemm_kernel,
                         cudaFuncAttributeMaxDynamicSharedMemorySize, SMEM_SZ);

    for (int l = 0; l < 3; l++) {
        const float* grid = (const float*)d_in[1 + 4 * l];
        const float* coef = (const float*)d_in[2 + 4 * l];
        const float* sbp  = (const float*)d_in[3 + 4 * l];
        const float* spp  = (const float*)d_in[4 + 4 * l];

        fold_kernel<<<dim3(OUT / FO, IN / FI), 256>>>(coef, sbp, spp);
        if (l == 0)
            phi_first<<<(BATCH * IN + 255) / 256, 256>>>((const float*)d_in[0], grid);
        else
            phi_fused<<<(BATCH * IN + 255) / 256, 256>>>(pptr, grid);
        gemm_kernel<<<dim3(OUT / BN, BATCH / BM, KSPLIT), 256, SMEM_SZ>>>(
            Aptr, Bptr, pptr);
    }
    reduce_kernel<<<(BATCH * OUT / 4 + 255) / 256, 256>>>(pptr, (float*)d_out);
}